// round 1
// baseline (speedup 1.0000x reference)
#include <cuda_runtime.h>
#include <math.h>

// Problem constants
#define MROWS  16384   // B*T*S = 32*512
#define DMODEL 768
#define SEQ    512
#define NHEAD  12
#define HDIM   64
#define NBATCH 384     // (B*T)*H = 32*12

// ---------------- scratch (static device memory; no allocation) --------------
__device__ float g_Q  [(size_t)NBATCH * SEQ * HDIM];   // [b*h][s][d]  (pre-scaled)
__device__ float g_Kt [(size_t)NBATCH * HDIM * SEQ];   // [b*h][d][s]  (transposed)
__device__ float g_V  [(size_t)NBATCH * SEQ * HDIM];   // [b*h][s][d]
__device__ float g_P  [(size_t)NBATCH * SEQ * SEQ];    // scores / probs
__device__ float g_CTX[(size_t)MROWS * DMODEL];        // [row][h*64+d]

// =============================================================================
// Generic 128x128x(K=768) fp32 GEMM: C = A(16384x768) @ W(768x768) + bias
// mode 0: scatter to g_Q  (scaled by 1/sqrt(64))
// mode 1: scatter to g_Kt (transposed layout)
// mode 2: scatter to g_V
// mode 3: A := g_CTX, plain row-major store to `out` (final output)
// =============================================================================
__global__ __launch_bounds__(256) void gemm768(
    const float* __restrict__ A_in, const float* __restrict__ W,
    const float* __restrict__ bias, float* __restrict__ out, int mode)
{
    __shared__ float sA[16 * 132];   // [k][m], padded stride 132
    __shared__ float sB[16 * 128];   // [k][n]

    const float* __restrict__ A = (mode == 3) ? (const float*)g_CTX : A_in;

    const int tid = threadIdx.x;
    const int tx = tid & 15;         // 0..15 -> 8 output cols (2 quadrants x4)
    const int ty = tid >> 4;         // 0..15 -> 8 output rows
    const int m0 = blockIdx.y * 128;
    const int n0 = blockIdx.x * 128;

    float acc[8][8];
#pragma unroll
    for (int i = 0; i < 8; i++)
#pragma unroll
        for (int j = 0; j < 8; j++) acc[i][j] = 0.0f;

    for (int k0 = 0; k0 < DMODEL; k0 += 16) {
        // load A tile 128x16 -> sA[k][m]
#pragma unroll
        for (int rep = 0; rep < 2; rep++) {
            int e = rep * 256 + tid;
            int r = e >> 2, c4 = e & 3;
            float4 a = *(const float4*)(A + (size_t)(m0 + r) * DMODEL + k0 + c4 * 4);
            sA[(c4 * 4 + 0) * 132 + r] = a.x;
            sA[(c4 * 4 + 1) * 132 + r] = a.y;
            sA[(c4 * 4 + 2) * 132 + r] = a.z;
            sA[(c4 * 4 + 3) * 132 + r] = a.w;
        }
        // load B tile 16x128 -> sB[k][n]
#pragma unroll
        for (int rep = 0; rep < 2; rep++) {
            int e = rep * 256 + tid;
            int r = e >> 5, c4 = e & 31;
            *(float4*)(sB + r * 128 + c4 * 4) =
                *(const float4*)(W + (size_t)(k0 + r) * DMODEL + n0 + c4 * 4);
        }
        __syncthreads();
#pragma unroll
        for (int k = 0; k < 16; k++) {
            float ar[8], br[8];
            float4 t;
            t = *(const float4*)(sA + k * 132 + ty * 4);
            ar[0] = t.x; ar[1] = t.y; ar[2] = t.z; ar[3] = t.w;
            t = *(const float4*)(sA + k * 132 + 64 + ty * 4);
            ar[4] = t.x; ar[5] = t.y; ar[6] = t.z; ar[7] = t.w;
            t = *(const float4*)(sB + k * 128 + tx * 4);
            br[0] = t.x; br[1] = t.y; br[2] = t.z; br[3] = t.w;
            t = *(const float4*)(sB + k * 128 + 64 + tx * 4);
            br[4] = t.x; br[5] = t.y; br[6] = t.z; br[7] = t.w;
#pragma unroll
            for (int i = 0; i < 8; i++)
#pragma unroll
                for (int j = 0; j < 8; j++) acc[i][j] += ar[i] * br[j];
        }
        __syncthreads();
    }

    // epilogue
#pragma unroll
    for (int i = 0; i < 8; i++) {
        int m = m0 + ((i < 4) ? (ty * 4 + i) : (64 + ty * 4 + (i - 4)));
        int bt = m >> 9, s = m & 511;
#pragma unroll
        for (int j = 0; j < 8; j++) {
            int n = n0 + ((j < 4) ? (tx * 4 + j) : (64 + tx * 4 + (j - 4)));
            float v = acc[i][j] + bias[n];
            int h = n >> 6, d = n & 63;
            if (mode == 0) {
                g_Q[(size_t)((bt * NHEAD + h) * SEQ + s) * HDIM + d] = v * 0.125f;
            } else if (mode == 1) {
                g_Kt[(size_t)((bt * NHEAD + h) * HDIM + d) * SEQ + s] = v;
            } else if (mode == 2) {
                g_V[(size_t)((bt * NHEAD + h) * SEQ + s) * HDIM + d] = v;
            } else {
                out[(size_t)m * DMODEL + n] = v;
            }
        }
    }
}

// =============================================================================
// Scores: per batch (b*h): S[q][k] = Q[q,:] . Kt[:,k], masked.  M=N=512, K=64
// =============================================================================
__global__ __launch_bounds__(256) void scores_gemm(
    const int* __restrict__ mods, const int* __restrict__ nlp)
{
    __shared__ float sA[16 * 132];
    __shared__ float sB[16 * 128];

    const int tid = threadIdx.x;
    const int tx = tid & 15, ty = tid >> 4;
    const int batch = blockIdx.z;
    const int m0 = blockIdx.y * 128;   // query tile
    const int n0 = blockIdx.x * 128;   // key tile

    const float* __restrict__ A = g_Q  + (size_t)batch * SEQ * HDIM;   // lda=64
    const float* __restrict__ B = g_Kt + (size_t)batch * HDIM * SEQ;   // ldb=512
    float* __restrict__ C = g_P + (size_t)batch * SEQ * SEQ;

    float acc[8][8];
#pragma unroll
    for (int i = 0; i < 8; i++)
#pragma unroll
        for (int j = 0; j < 8; j++) acc[i][j] = 0.0f;

    for (int k0 = 0; k0 < HDIM; k0 += 16) {
#pragma unroll
        for (int rep = 0; rep < 2; rep++) {
            int e = rep * 256 + tid;
            int r = e >> 2, c4 = e & 3;
            float4 a = *(const float4*)(A + (size_t)(m0 + r) * HDIM + k0 + c4 * 4);
            sA[(c4 * 4 + 0) * 132 + r] = a.x;
            sA[(c4 * 4 + 1) * 132 + r] = a.y;
            sA[(c4 * 4 + 2) * 132 + r] = a.z;
            sA[(c4 * 4 + 3) * 132 + r] = a.w;
        }
#pragma unroll
        for (int rep = 0; rep < 2; rep++) {
            int e = rep * 256 + tid;
            int r = e >> 5, c4 = e & 31;
            *(float4*)(sB + r * 128 + c4 * 4) =
                *(const float4*)(B + (size_t)(k0 + r) * SEQ + n0 + c4 * 4);
        }
        __syncthreads();
#pragma unroll
        for (int k = 0; k < 16; k++) {
            float ar[8], br[8];
            float4 t;
            t = *(const float4*)(sA + k * 132 + ty * 4);
            ar[0] = t.x; ar[1] = t.y; ar[2] = t.z; ar[3] = t.w;
            t = *(const float4*)(sA + k * 132 + 64 + ty * 4);
            ar[4] = t.x; ar[5] = t.y; ar[6] = t.z; ar[7] = t.w;
            t = *(const float4*)(sB + k * 128 + tx * 4);
            br[0] = t.x; br[1] = t.y; br[2] = t.z; br[3] = t.w;
            t = *(const float4*)(sB + k * 128 + 64 + tx * 4);
            br[4] = t.x; br[5] = t.y; br[6] = t.z; br[7] = t.w;
#pragma unroll
            for (int i = 0; i < 8; i++)
#pragma unroll
                for (int j = 0; j < 8; j++) acc[i][j] += ar[i] * br[j];
        }
        __syncthreads();
    }

    const int nlat = nlp ? *nlp : 32;
#pragma unroll
    for (int i = 0; i < 8; i++) {
        int q = m0 + ((i < 4) ? (ty * 4 + i) : (64 + ty * 4 + (i - 4)));
        bool qlat = (q < nlat);
        int mq = mods[q];
#pragma unroll
        for (int j = 0; j < 8; j++) {
            int key = n0 + ((j < 4) ? (tx * 4 + j) : (64 + tx * 4 + (j - 4)));
            bool ok = qlat || (mq == mods[key]);
            C[(size_t)q * SEQ + key] = ok ? acc[i][j] : -1.0e30f;
        }
    }
}

// =============================================================================
// Row softmax over 512 keys.  1 warp per row, 8 rows per block.
// =============================================================================
__global__ __launch_bounds__(256) void softmax_k()
{
    const int warp = threadIdx.x >> 5, lane = threadIdx.x & 31;
    const size_t row = (size_t)blockIdx.x * 8 + warp;
    float* __restrict__ p = g_P + row * SEQ;

    float v[16];
    float mx = -3.0e38f;
#pragma unroll
    for (int j = 0; j < 16; j++) {
        v[j] = p[lane + j * 32];
        mx = fmaxf(mx, v[j]);
    }
#pragma unroll
    for (int off = 16; off >= 1; off >>= 1)
        mx = fmaxf(mx, __shfl_xor_sync(0xffffffffu, mx, off));

    float sum = 0.0f;
#pragma unroll
    for (int j = 0; j < 16; j++) {
        v[j] = __expf(v[j] - mx);
        sum += v[j];
    }
#pragma unroll
    for (int off = 16; off >= 1; off >>= 1)
        sum += __shfl_xor_sync(0xffffffffu, sum, off);

    const float inv = 1.0f / sum;
#pragma unroll
    for (int j = 0; j < 16; j++) p[lane + j * 32] = v[j] * inv;
}

// =============================================================================
// ctx = P @ V per batch:  M=512, N=64, K=512.  BM=128, BN=64, thread tile 8x4.
// Writes ctx into g_CTX[row][h*64+d] so the final GEMM is a plain row-major GEMM.
// =============================================================================
__global__ __launch_bounds__(256) void ctx_gemm()
{
    __shared__ float sA[16 * 132];
    __shared__ float sB[16 * 64];

    const int tid = threadIdx.x;
    const int tx = tid & 15, ty = tid >> 4;
    const int batch = blockIdx.y;
    const int m0 = blockIdx.x * 128;

    const float* __restrict__ A  = g_P + (size_t)batch * SEQ * SEQ;   // lda=512
    const float* __restrict__ Bv = g_V + (size_t)batch * SEQ * HDIM;  // ldb=64

    float acc[8][4];
#pragma unroll
    for (int i = 0; i < 8; i++)
#pragma unroll
        for (int j = 0; j < 4; j++) acc[i][j] = 0.0f;

    for (int k0 = 0; k0 < SEQ; k0 += 16) {
#pragma unroll
        for (int rep = 0; rep < 2; rep++) {
            int e = rep * 256 + tid;
            int r = e >> 2, c4 = e & 3;
            float4 a = *(const float4*)(A + (size_t)(m0 + r) * SEQ + k0 + c4 * 4);
            sA[(c4 * 4 + 0) * 132 + r] = a.x;
            sA[(c4 * 4 + 1) * 132 + r] = a.y;
            sA[(c4 * 4 + 2) * 132 + r] = a.z;
            sA[(c4 * 4 + 3) * 132 + r] = a.w;
        }
        {
            int r = tid >> 4, c4 = tid & 15;
            *(float4*)(sB + r * 64 + c4 * 4) =
                *(const float4*)(Bv + (size_t)(k0 + r) * HDIM + c4 * 4);
        }
        __syncthreads();
#pragma unroll
        for (int k = 0; k < 16; k++) {
            float ar[8], br[4];
            float4 t;
            t = *(const float4*)(sA + k * 132 + ty * 4);
            ar[0] = t.x; ar[1] = t.y; ar[2] = t.z; ar[3] = t.w;
            t = *(const float4*)(sA + k * 132 + 64 + ty * 4);
            ar[4] = t.x; ar[5] = t.y; ar[6] = t.z; ar[7] = t.w;
            t = *(const float4*)(sB + k * 64 + tx * 4);
            br[0] = t.x; br[1] = t.y; br[2] = t.z; br[3] = t.w;
#pragma unroll
            for (int i = 0; i < 8; i++)
#pragma unroll
                for (int j = 0; j < 4; j++) acc[i][j] += ar[i] * br[j];
        }
        __syncthreads();
    }

    const int bt = batch / NHEAD, h = batch % NHEAD;
#pragma unroll
    for (int i = 0; i < 8; i++) {
        int q = m0 + ((i < 4) ? (ty * 4 + i) : (64 + ty * 4 + (i - 4)));
#pragma unroll
        for (int j = 0; j < 4; j++) {
            int d = tx * 4 + j;
            g_CTX[(size_t)(bt * SEQ + q) * DMODEL + h * HDIM + d] = acc[i][j];
        }
    }
}

// =============================================================================
extern "C" void kernel_launch(void* const* d_in, const int* in_sizes, int n_in,
                              void* d_out, int out_size)
{
    const float* x  = (const float*)d_in[0];
    const float* Wq = (const float*)d_in[1];
    const float* bq = (const float*)d_in[2];
    const float* Wk = (const float*)d_in[3];
    const float* bk = (const float*)d_in[4];
    const float* Wv = (const float*)d_in[5];
    const float* bv = (const float*)d_in[6];
    const float* Wo = (const float*)d_in[7];
    const float* bo = (const float*)d_in[8];
    const int* mods = (const int*)d_in[9];
    const int* nlp  = (n_in > 10) ? (const int*)d_in[10] : nullptr;
    float* out = (float*)d_out;

    dim3 blk(256);
    gemm768<<<dim3(6, 128), blk>>>(x, Wq, bq, nullptr, 0);
    gemm768<<<dim3(6, 128), blk>>>(x, Wk, bk, nullptr, 1);
    gemm768<<<dim3(6, 128), blk>>>(x, Wv, bv, nullptr, 2);
    scores_gemm<<<dim3(4, 4, NBATCH), blk>>>(mods, nlp);
    softmax_k<<<dim3((NBATCH * SEQ) / 8), blk>>>();
    ctx_gemm<<<dim3(4, NBATCH), blk>>>();
    gemm768<<<dim3(6, 128), blk>>>(nullptr, Wo, bo, out, 3);
}

// round 3
// speedup vs baseline: 2.0085x; 2.0085x over previous
#include <cuda_runtime.h>
#include <math.h>

// Problem constants
#define MROWS  16384   // B*T*S = 32*512
#define DMODEL 768
#define SEQ    512
#define NHEAD  12
#define HDIM   64
#define NBATCH 384     // (B*T)*H = 32*12

#define SSTR   136     // smem row stride (words); 136 % 32 == 8 -> conflict-free frag loads

// ---------------- scratch (static device memory; no allocation) --------------
__device__ float g_Q  [(size_t)NBATCH * SEQ * HDIM];   // [b*h][s][d]  (pre-scaled)
__device__ float g_Kt [(size_t)NBATCH * HDIM * SEQ];   // [b*h][d][s]  (transposed)
__device__ float g_V  [(size_t)NBATCH * SEQ * HDIM];   // [b*h][s][d]
__device__ float g_P  [(size_t)NBATCH * SEQ * SEQ];    // scores / probs
__device__ float g_CTX[(size_t)MROWS * DMODEL];        // [row][h*64+d]

// ---------------- tf32 helpers ----------------
__device__ __forceinline__ unsigned f2tf(float f) {
    unsigned u;
    asm("cvt.rna.tf32.f32 %0, %1;" : "=r"(u) : "f"(f));
    return u;
}

#define MMA_TF32(d, a, b)                                                          \
    asm volatile(                                                                  \
        "mma.sync.aligned.m16n8k8.row.col.f32.tf32.tf32.f32 "                      \
        "{%0,%1,%2,%3}, {%4,%5,%6,%7}, {%8,%9}, {%0,%1,%2,%3};"                    \
        : "+f"((d)[0]), "+f"((d)[1]), "+f"((d)[2]), "+f"((d)[3])                   \
        : "r"((a)[0]), "r"((a)[1]), "r"((a)[2]), "r"((a)[3]),                      \
          "r"((b)[0]), "r"((b)[1]))

// scatter for the big projection GEMM epilogues
__device__ __forceinline__ void scatter(int mode, int m, int n, float v,
                                        float* __restrict__ out) {
    int bt = m >> 9, s = m & 511;
    int h = n >> 6, d = n & 63;
    if (mode == 0) {
        g_Q[((size_t)(bt * NHEAD + h) * SEQ + s) * HDIM + d] = v * 0.125f;
    } else if (mode == 1) {
        g_Kt[((size_t)(bt * NHEAD + h) * HDIM + d) * SEQ + s] = v;
    } else if (mode == 2) {
        g_V[((size_t)(bt * NHEAD + h) * SEQ + s) * HDIM + d] = v;
    } else {
        out[(size_t)m * DMODEL + n] = v;
    }
}

// =============================================================================
// 128x128 tf32-MMA GEMM over K=768: C = A(16384x768) @ W(768x768) + bias
// 256 threads = 8 warps; warp grid 2(m) x 4(n); warp tile 64x32; frag 16x8x8.
// =============================================================================
__global__ __launch_bounds__(256) void gemm768(
    const float* __restrict__ A_in, const float* __restrict__ W,
    const float* __restrict__ bias, float* __restrict__ out, int mode)
{
    __shared__ unsigned sA[16 * SSTR];   // [k][m] tf32 bits
    __shared__ unsigned sB[16 * SSTR];   // [k][n] tf32 bits

    const float* __restrict__ A = (mode == 3) ? (const float*)g_CTX : A_in;

    const int tid  = threadIdx.x;
    const int lane = tid & 31, warp = tid >> 5;
    const int wm = warp & 1, wn = warp >> 1;        // 2 x 4 warp grid
    const int grp = lane >> 2, tig = lane & 3;
    const int m0 = blockIdx.y * 128;
    const int n0 = blockIdx.x * 128;

    float acc[4][4][4];
#pragma unroll
    for (int i = 0; i < 4; i++)
#pragma unroll
        for (int j = 0; j < 4; j++)
#pragma unroll
            for (int e = 0; e < 4; e++) acc[i][j][e] = 0.0f;

    for (int k0 = 0; k0 < DMODEL; k0 += 16) {
        // A tile 128x16 -> sA[k][m]
#pragma unroll
        for (int rep = 0; rep < 2; rep++) {
            int e = rep * 256 + tid;
            int r = e >> 2, c4 = e & 3;
            float4 a = *(const float4*)(A + (size_t)(m0 + r) * DMODEL + k0 + c4 * 4);
            sA[(c4 * 4 + 0) * SSTR + r] = f2tf(a.x);
            sA[(c4 * 4 + 1) * SSTR + r] = f2tf(a.y);
            sA[(c4 * 4 + 2) * SSTR + r] = f2tf(a.z);
            sA[(c4 * 4 + 3) * SSTR + r] = f2tf(a.w);
        }
        // B tile 16x128 -> sB[k][n]
#pragma unroll
        for (int rep = 0; rep < 2; rep++) {
            int e = rep * 256 + tid;
            int r = e >> 5, c = (e & 31) * 4;
            float4 b = *(const float4*)(W + (size_t)(k0 + r) * DMODEL + n0 + c);
            sB[r * SSTR + c + 0] = f2tf(b.x);
            sB[r * SSTR + c + 1] = f2tf(b.y);
            sB[r * SSTR + c + 2] = f2tf(b.z);
            sB[r * SSTR + c + 3] = f2tf(b.w);
        }
        __syncthreads();

#pragma unroll
        for (int kk = 0; kk < 16; kk += 8) {
            unsigned af[4][4], bf[4][2];
#pragma unroll
            for (int mi = 0; mi < 4; mi++) {
                int m = wm * 64 + mi * 16 + grp;
                af[mi][0] = sA[(kk + tig) * SSTR + m];
                af[mi][1] = sA[(kk + tig) * SSTR + m + 8];
                af[mi][2] = sA[(kk + tig + 4) * SSTR + m];
                af[mi][3] = sA[(kk + tig + 4) * SSTR + m + 8];
            }
#pragma unroll
            for (int nj = 0; nj < 4; nj++) {
                int n = wn * 32 + nj * 8 + grp;
                bf[nj][0] = sB[(kk + tig) * SSTR + n];
                bf[nj][1] = sB[(kk + tig + 4) * SSTR + n];
            }
#pragma unroll
            for (int mi = 0; mi < 4; mi++)
#pragma unroll
                for (int nj = 0; nj < 4; nj++)
                    MMA_TF32(acc[mi][nj], af[mi], bf[nj]);
        }
        __syncthreads();
    }

    // epilogue
#pragma unroll
    for (int mi = 0; mi < 4; mi++) {
        int r0 = m0 + wm * 64 + mi * 16 + grp;
#pragma unroll
        for (int nj = 0; nj < 4; nj++) {
            int c0 = n0 + wn * 32 + nj * 8 + tig * 2;
            scatter(mode, r0,     c0,     acc[mi][nj][0] + bias[c0],     out);
            scatter(mode, r0,     c0 + 1, acc[mi][nj][1] + bias[c0 + 1], out);
            scatter(mode, r0 + 8, c0,     acc[mi][nj][2] + bias[c0],     out);
            scatter(mode, r0 + 8, c0 + 1, acc[mi][nj][3] + bias[c0 + 1], out);
        }
    }
}

// =============================================================================
// Scores: per batch, S[q][k] = Q[q,:] . Kt[:,k] with modality mask. M=N=512,K=64
// =============================================================================
__global__ __launch_bounds__(256) void scores_gemm(
    const int* __restrict__ mods, const int* __restrict__ nlp)
{
    __shared__ unsigned sA[16 * SSTR];
    __shared__ unsigned sB[16 * SSTR];

    const int tid  = threadIdx.x;
    const int lane = tid & 31, warp = tid >> 5;
    const int wm = warp & 1, wn = warp >> 1;
    const int grp = lane >> 2, tig = lane & 3;
    const int batch = blockIdx.z;
    const int m0 = blockIdx.y * 128;
    const int n0 = blockIdx.x * 128;

    const float* __restrict__ A = g_Q  + (size_t)batch * SEQ * HDIM;   // lda=64
    const float* __restrict__ B = g_Kt + (size_t)batch * HDIM * SEQ;   // ldb=512
    float* __restrict__ C = g_P + (size_t)batch * SEQ * SEQ;

    float acc[4][4][4];
#pragma unroll
    for (int i = 0; i < 4; i++)
#pragma unroll
        for (int j = 0; j < 4; j++)
#pragma unroll
            for (int e = 0; e < 4; e++) acc[i][j][e] = 0.0f;

    for (int k0 = 0; k0 < HDIM; k0 += 16) {
#pragma unroll
        for (int rep = 0; rep < 2; rep++) {
            int e = rep * 256 + tid;
            int r = e >> 2, c4 = e & 3;
            float4 a = *(const float4*)(A + (size_t)(m0 + r) * HDIM + k0 + c4 * 4);
            sA[(c4 * 4 + 0) * SSTR + r] = f2tf(a.x);
            sA[(c4 * 4 + 1) * SSTR + r] = f2tf(a.y);
            sA[(c4 * 4 + 2) * SSTR + r] = f2tf(a.z);
            sA[(c4 * 4 + 3) * SSTR + r] = f2tf(a.w);
        }
#pragma unroll
        for (int rep = 0; rep < 2; rep++) {
            int e = rep * 256 + tid;
            int r = e >> 5, c = (e & 31) * 4;
            float4 b = *(const float4*)(B + (size_t)(k0 + r) * SEQ + n0 + c);
            sB[r * SSTR + c + 0] = f2tf(b.x);
            sB[r * SSTR + c + 1] = f2tf(b.y);
            sB[r * SSTR + c + 2] = f2tf(b.z);
            sB[r * SSTR + c + 3] = f2tf(b.w);
        }
        __syncthreads();

#pragma unroll
        for (int kk = 0; kk < 16; kk += 8) {
            unsigned af[4][4], bf[4][2];
#pragma unroll
            for (int mi = 0; mi < 4; mi++) {
                int m = wm * 64 + mi * 16 + grp;
                af[mi][0] = sA[(kk + tig) * SSTR + m];
                af[mi][1] = sA[(kk + tig) * SSTR + m + 8];
                af[mi][2] = sA[(kk + tig + 4) * SSTR + m];
                af[mi][3] = sA[(kk + tig + 4) * SSTR + m + 8];
            }
#pragma unroll
            for (int nj = 0; nj < 4; nj++) {
                int n = wn * 32 + nj * 8 + grp;
                bf[nj][0] = sB[(kk + tig) * SSTR + n];
                bf[nj][1] = sB[(kk + tig + 4) * SSTR + n];
            }
#pragma unroll
            for (int mi = 0; mi < 4; mi++)
#pragma unroll
                for (int nj = 0; nj < 4; nj++)
                    MMA_TF32(acc[mi][nj], af[mi], bf[nj]);
        }
        __syncthreads();
    }

    const int nlat = nlp ? *nlp : 32;
#pragma unroll
    for (int mi = 0; mi < 4; mi++) {
        int q0 = m0 + wm * 64 + mi * 16 + grp;
#pragma unroll
        for (int rr = 0; rr < 2; rr++) {
            int q = q0 + rr * 8;
            bool qlat = (q < nlat);
            int mq = mods[q];
#pragma unroll
            for (int nj = 0; nj < 4; nj++) {
                int c0 = n0 + wn * 32 + nj * 8 + tig * 2;
                bool ok0 = qlat || (mq == mods[c0]);
                bool ok1 = qlat || (mq == mods[c0 + 1]);
                C[(size_t)q * SEQ + c0]     = ok0 ? acc[mi][nj][rr * 2]     : -1.0e30f;
                C[(size_t)q * SEQ + c0 + 1] = ok1 ? acc[mi][nj][rr * 2 + 1] : -1.0e30f;
            }
        }
    }
}

// =============================================================================
// Row softmax over 512 keys.  1 warp per row, 8 rows per block.
// =============================================================================
__global__ __launch_bounds__(256) void softmax_k()
{
    const int warp = threadIdx.x >> 5, lane = threadIdx.x & 31;
    const size_t row = (size_t)blockIdx.x * 8 + warp;
    float* __restrict__ p = g_P + row * SEQ;

    float v[16];
    float mx = -3.0e38f;
#pragma unroll
    for (int j = 0; j < 16; j++) {
        v[j] = p[lane + j * 32];
        mx = fmaxf(mx, v[j]);
    }
#pragma unroll
    for (int off = 16; off >= 1; off >>= 1)
        mx = fmaxf(mx, __shfl_xor_sync(0xffffffffu, mx, off));

    float sum = 0.0f;
#pragma unroll
    for (int j = 0; j < 16; j++) {
        v[j] = __expf(v[j] - mx);
        sum += v[j];
    }
#pragma unroll
    for (int off = 16; off >= 1; off >>= 1)
        sum += __shfl_xor_sync(0xffffffffu, sum, off);

    const float inv = 1.0f / sum;
#pragma unroll
    for (int j = 0; j < 16; j++) p[lane + j * 32] = v[j] * inv;
}

// =============================================================================
// ctx = P @ V per batch: M=512, N=64, K=512.  BM=128, BN=64.
// 128 threads = 4 warps; warp grid 2(m) x 2(n); warp tile 64x32.
// =============================================================================
__global__ __launch_bounds__(128) void ctx_gemm()
{
    __shared__ unsigned sA[16 * SSTR];   // [k][m] P tile
    __shared__ unsigned sB[16 * SSTR];   // [k][n] V tile (n<=64)

    const int tid  = threadIdx.x;
    const int lane = tid & 31, warp = tid >> 5;
    const int wm = warp & 1, wn = warp >> 1;
    const int grp = lane >> 2, tig = lane & 3;
    const int batch = blockIdx.y;
    const int m0 = blockIdx.x * 128;

    const float* __restrict__ A  = g_P + (size_t)batch * SEQ * SEQ;   // lda=512
    const float* __restrict__ Bv = g_V + (size_t)batch * SEQ * HDIM;  // ldb=64

    float acc[4][4][4];
#pragma unroll
    for (int i = 0; i < 4; i++)
#pragma unroll
        for (int j = 0; j < 4; j++)
#pragma unroll
            for (int e = 0; e < 4; e++) acc[i][j][e] = 0.0f;

    for (int k0 = 0; k0 < SEQ; k0 += 16) {
#pragma unroll
        for (int rep = 0; rep < 4; rep++) {
            int e = rep * 128 + tid;
            int r = e >> 2, c4 = e & 3;
            float4 a = *(const float4*)(A + (size_t)(m0 + r) * SEQ + k0 + c4 * 4);
            sA[(c4 * 4 + 0) * SSTR + r] = f2tf(a.x);
            sA[(c4 * 4 + 1) * SSTR + r] = f2tf(a.y);
            sA[(c4 * 4 + 2) * SSTR + r] = f2tf(a.z);
            sA[(c4 * 4 + 3) * SSTR + r] = f2tf(a.w);
        }
#pragma unroll
        for (int rep = 0; rep < 2; rep++) {
            int e = rep * 128 + tid;
            int r = e >> 4, c = (e & 15) * 4;
            float4 b = *(const float4*)(Bv + (size_t)(k0 + r) * HDIM + c);
            sB[r * SSTR + c + 0] = f2tf(b.x);
            sB[r * SSTR + c + 1] = f2tf(b.y);
            sB[r * SSTR + c + 2] = f2tf(b.z);
            sB[r * SSTR + c + 3] = f2tf(b.w);
        }
        __syncthreads();

#pragma unroll
        for (int kk = 0; kk < 16; kk += 8) {
            unsigned af[4][4], bf[4][2];
#pragma unroll
            for (int mi = 0; mi < 4; mi++) {
                int m = wm * 64 + mi * 16 + grp;
                af[mi][0] = sA[(kk + tig) * SSTR + m];
                af[mi][1] = sA[(kk + tig) * SSTR + m + 8];
                af[mi][2] = sA[(kk + tig + 4) * SSTR + m];
                af[mi][3] = sA[(kk + tig + 4) * SSTR + m + 8];
            }
#pragma unroll
            for (int nj = 0; nj < 4; nj++) {
                int n = wn * 32 + nj * 8 + grp;
                bf[nj][0] = sB[(kk + tig) * SSTR + n];
                bf[nj][1] = sB[(kk + tig + 4) * SSTR + n];
            }
#pragma unroll
            for (int mi = 0; mi < 4; mi++)
#pragma unroll
                for (int nj = 0; nj < 4; nj++)
                    MMA_TF32(acc[mi][nj], af[mi], bf[nj]);
        }
        __syncthreads();
    }

    const int bt = batch / NHEAD, h = batch % NHEAD;
#pragma unroll
    for (int mi = 0; mi < 4; mi++) {
        int q0 = m0 + wm * 64 + mi * 16 + grp;
#pragma unroll
        for (int nj = 0; nj < 4; nj++) {
            int d0 = wn * 32 + nj * 8 + tig * 2;
            g_CTX[(size_t)(bt * SEQ + q0) * DMODEL + h * HDIM + d0]         = acc[mi][nj][0];
            g_CTX[(size_t)(bt * SEQ + q0) * DMODEL + h * HDIM + d0 + 1]     = acc[mi][nj][1];
            g_CTX[(size_t)(bt * SEQ + q0 + 8) * DMODEL + h * HDIM + d0]     = acc[mi][nj][2];
            g_CTX[(size_t)(bt * SEQ + q0 + 8) * DMODEL + h * HDIM + d0 + 1] = acc[mi][nj][3];
        }
    }
}

// =============================================================================
extern "C" void kernel_launch(void* const* d_in, const int* in_sizes, int n_in,
                              void* d_out, int out_size)
{
    const float* x  = (const float*)d_in[0];
    const float* Wq = (const float*)d_in[1];
    const float* bq = (const float*)d_in[2];
    const float* Wk = (const float*)d_in[3];
    const float* bk = (const float*)d_in[4];
    const float* Wv = (const float*)d_in[5];
    const float* bv = (const float*)d_in[6];
    const float* Wo = (const float*)d_in[7];
    const float* bo = (const float*)d_in[8];
    const int* mods = (const int*)d_in[9];
    const int* nlp  = (n_in > 10) ? (const int*)d_in[10] : nullptr;
    float* out = (float*)d_out;

    gemm768<<<dim3(6, 128), 256>>>(x, Wq, bq, nullptr, 0);
    gemm768<<<dim3(6, 128), 256>>>(x, Wk, bk, nullptr, 1);
    gemm768<<<dim3(6, 128), 256>>>(x, Wv, bv, nullptr, 2);
    scores_gemm<<<dim3(4, 4, NBATCH), 256>>>(mods, nlp);
    softmax_k<<<dim3((NBATCH * SEQ) / 8), 256>>>();
    ctx_gemm<<<dim3(4, NBATCH), 128>>>();
    gemm768<<<dim3(6, 128), 256>>>(nullptr, Wo, bo, out, 3);
}

// round 4
// speedup vs baseline: 2.2000x; 1.0954x over previous
#include <cuda_runtime.h>
#include <math.h>

// Problem constants
#define MROWS  16384   // B*T*S = 32*512
#define DMODEL 768
#define SEQ    512
#define NHEAD  12
#define HDIM   64
#define NBATCH 384     // (B*T)*H = 32*12

// ---------------- scratch (static device memory; no allocation) --------------
__device__ float g_Q  [(size_t)NBATCH * SEQ * HDIM];   // [b*h][s][d]  (pre-scaled)
__device__ float g_Kt [(size_t)NBATCH * HDIM * SEQ];   // [b*h][d][s]  (transposed)
__device__ float g_V  [(size_t)NBATCH * SEQ * HDIM];   // [b*h][s][d]
__device__ float g_CTX[(size_t)MROWS * DMODEL];        // [row][h*64+d]

// ---------------- helpers ----------------
__device__ __forceinline__ unsigned f2tf(float f) {
    unsigned u;
    asm("cvt.rna.tf32.f32 %0, %1;" : "=r"(u) : "f"(f));
    return u;
}

__device__ __forceinline__ void cp16(unsigned dst, const void* src) {
    asm volatile("cp.async.ca.shared.global [%0], [%1], 16;" :: "r"(dst), "l"(src));
}

#define MMA_TF32(d, a, b)                                                          \
    asm volatile(                                                                  \
        "mma.sync.aligned.m16n8k8.row.col.f32.tf32.tf32.f32 "                      \
        "{%0,%1,%2,%3}, {%4,%5,%6,%7}, {%8,%9}, {%0,%1,%2,%3};"                    \
        : "+f"((d)[0]), "+f"((d)[1]), "+f"((d)[2]), "+f"((d)[3])                   \
        : "r"((a)[0]), "r"((a)[1]), "r"((a)[2]), "r"((a)[3]),                      \
          "r"((b)[0]), "r"((b)[1]))

// scatter for projection GEMM epilogues
__device__ __forceinline__ void scatter(int mode, int m, int n, float v,
                                        float* __restrict__ out) {
    int bt = m >> 9, s = m & 511;
    int h = n >> 6, d = n & 63;
    if (mode == 0) {
        g_Q[((size_t)(bt * NHEAD + h) * SEQ + s) * HDIM + d] = v * 0.125f;
    } else if (mode == 1) {
        g_Kt[((size_t)(bt * NHEAD + h) * HDIM + d) * SEQ + s] = v;
    } else if (mode == 2) {
        g_V[((size_t)(bt * NHEAD + h) * SEQ + s) * HDIM + d] = v;
    } else {
        out[(size_t)m * DMODEL + n] = v;
    }
}

// =============================================================================
// 128x128 tf32-MMA GEMM over K=768, cp.async double-buffered.
// 256 threads = 8 warps; warp grid 2(m) x 4(n); warp tile 64x32.
// smem: raw fp32 tiles; cvt.rna at fragment load.
// sA: [m][k] stride 20 (conflict-free frag loads); sB: [k][n] stride 136.
// =============================================================================
#define SA_STR 20
#define SB_STR 136
#define SA_SZ  (128 * SA_STR)
#define SB_SZ  (16 * SB_STR)

__global__ __launch_bounds__(256) void gemm768(
    const float* __restrict__ A_in, const float* __restrict__ W,
    const float* __restrict__ bias, float* __restrict__ out, int mode)
{
    __shared__ float sA[2 * SA_SZ];
    __shared__ float sB[2 * SB_SZ];

    const float* __restrict__ A = (mode == 3) ? (const float*)g_CTX : A_in;

    const int tid  = threadIdx.x;
    const int lane = tid & 31, warp = tid >> 5;
    const int wm = warp & 1, wn = warp >> 1;
    const int grp = lane >> 2, tig = lane & 3;
    const int m0 = blockIdx.y * 128;
    const int n0 = blockIdx.x * 128;

    const unsigned sA_u32 = (unsigned)__cvta_generic_to_shared(sA);
    const unsigned sB_u32 = (unsigned)__cvta_generic_to_shared(sB);

    float acc[4][4][4];
#pragma unroll
    for (int i = 0; i < 4; i++)
#pragma unroll
        for (int j = 0; j < 4; j++)
#pragma unroll
            for (int e = 0; e < 4; e++) acc[i][j][e] = 0.0f;

#define G_LOAD_TILES(buf, k0)                                                     \
    {                                                                             \
        _Pragma("unroll")                                                         \
        for (int rep = 0; rep < 2; rep++) {                                       \
            int t = rep * 256 + tid;                                              \
            int r = t >> 2, c4 = (t & 3) * 4;                                     \
            cp16(sA_u32 + (unsigned)(((buf) * SA_SZ + r * SA_STR + c4) * 4),      \
                 A + (size_t)(m0 + r) * DMODEL + (k0) + c4);                      \
        }                                                                         \
        _Pragma("unroll")                                                         \
        for (int rep = 0; rep < 2; rep++) {                                       \
            int t = rep * 256 + tid;                                              \
            int r = t >> 5, c4 = (t & 31) * 4;                                    \
            cp16(sB_u32 + (unsigned)(((buf) * SB_SZ + r * SB_STR + c4) * 4),      \
                 W + (size_t)((k0) + r) * DMODEL + n0 + c4);                      \
        }                                                                         \
        asm volatile("cp.async.commit_group;" ::: "memory");                      \
    }

    G_LOAD_TILES(0, 0);

    int buf = 0;
    for (int k0 = 0; k0 < DMODEL; k0 += 16) {
        asm volatile("cp.async.wait_group 0;" ::: "memory");
        __syncthreads();
        if (k0 + 16 < DMODEL) G_LOAD_TILES(buf ^ 1, k0 + 16);

        const float* pA = sA + buf * SA_SZ;
        const float* pB = sB + buf * SB_SZ;
#pragma unroll
        for (int kk = 0; kk < 16; kk += 8) {
            unsigned af[4][4], bf[4][2];
#pragma unroll
            for (int mi = 0; mi < 4; mi++) {
                int m = wm * 64 + mi * 16 + grp;
                af[mi][0] = f2tf(pA[m * SA_STR + kk + tig]);
                af[mi][1] = f2tf(pA[(m + 8) * SA_STR + kk + tig]);
                af[mi][2] = f2tf(pA[m * SA_STR + kk + tig + 4]);
                af[mi][3] = f2tf(pA[(m + 8) * SA_STR + kk + tig + 4]);
            }
#pragma unroll
            for (int nj = 0; nj < 4; nj++) {
                int n = wn * 32 + nj * 8 + grp;
                bf[nj][0] = f2tf(pB[(kk + tig) * SB_STR + n]);
                bf[nj][1] = f2tf(pB[(kk + tig + 4) * SB_STR + n]);
            }
#pragma unroll
            for (int mi = 0; mi < 4; mi++)
#pragma unroll
                for (int nj = 0; nj < 4; nj++)
                    MMA_TF32(acc[mi][nj], af[mi], bf[nj]);
        }
        buf ^= 1;
    }

    // epilogue
#pragma unroll
    for (int mi = 0; mi < 4; mi++) {
        int r0 = m0 + wm * 64 + mi * 16 + grp;
#pragma unroll
        for (int nj = 0; nj < 4; nj++) {
            int c0 = n0 + wn * 32 + nj * 8 + tig * 2;
            scatter(mode, r0,     c0,     acc[mi][nj][0] + bias[c0],     out);
            scatter(mode, r0,     c0 + 1, acc[mi][nj][1] + bias[c0 + 1], out);
            scatter(mode, r0 + 8, c0,     acc[mi][nj][2] + bias[c0],     out);
            scatter(mode, r0 + 8, c0 + 1, acc[mi][nj][3] + bias[c0 + 1], out);
        }
    }
#undef G_LOAD_TILES
}

// =============================================================================
// Fused attention: per block = (one head-batch, 32 q rows).
// Phase 1: S(32x512) = Q @ K^T, kept in registers (32 floats/thread).
// Mask + full-row softmax (quad shuffle + cross-warp smem reduce).
// Phase 2: O(32x64) = P @ V, P round-trips smem in 64-key chunks.
// 512 threads = 16 warps; warp grid 2(m) x 8(n) for both phases.
// =============================================================================
#define QSTR 40
#define KSTR 72

__global__ __launch_bounds__(512) void attn_fused(
    const int* __restrict__ mods, const int* __restrict__ nlp)
{
    __shared__ int      s_mods[512];
    __shared__ float    s_red[16 * 32];
    __shared__ float    s_rmax[32];
    __shared__ float    s_rinv[32];
    __shared__ unsigned sQ[64 * QSTR];          // [d][q]
    __shared__ unsigned sU[64 * KSTR + 64 * QSTR];  // phase1: sK [d][key]; phase2: sP + sV

    const int tid  = threadIdx.x;
    const int lane = tid & 31, w = tid >> 5;
    const int grp  = lane >> 2, tig = lane & 3;
    const int wm = w & 1, wn = w >> 1;          // 2 x 8 warp grid
    const int batch = blockIdx.y;
    const int m0 = blockIdx.x * 32;
    const int bt = batch / NHEAD, h = batch % NHEAD;

    const float* __restrict__ Qp = g_Q  + (size_t)batch * SEQ * HDIM;
    const float* __restrict__ Kp = g_Kt + (size_t)batch * HDIM * SEQ;
    const float* __restrict__ Vp = g_V  + (size_t)batch * SEQ * HDIM;

    // modality ids + Q tile
    s_mods[tid] = mods[tid];
    {
        int q = tid >> 4, d4 = (tid & 15) * 4;
        float4 a = *(const float4*)(Qp + (size_t)(m0 + q) * HDIM + d4);
        sQ[(d4 + 0) * QSTR + q] = f2tf(a.x);
        sQ[(d4 + 1) * QSTR + q] = f2tf(a.y);
        sQ[(d4 + 2) * QSTR + q] = f2tf(a.z);
        sQ[(d4 + 3) * QSTR + q] = f2tf(a.w);
    }

    float S[8][4];
#pragma unroll
    for (int c = 0; c < 8; c++)
#pragma unroll
        for (int e = 0; e < 4; e++) S[c][e] = 0.0f;

    const int mloc = wm * 16 + grp;

    // ---------------- phase 1: S = Q @ K^T ----------------
#pragma unroll
    for (int c = 0; c < 8; c++) {
        __syncthreads();
#pragma unroll
        for (int rep = 0; rep < 2; rep++) {
            int t = rep * 512 + tid;
            int d = t >> 4, n4 = (t & 15) * 4;
            float4 kv = *(const float4*)(Kp + (size_t)d * SEQ + c * 64 + n4);
            sU[d * KSTR + n4 + 0] = f2tf(kv.x);
            sU[d * KSTR + n4 + 1] = f2tf(kv.y);
            sU[d * KSTR + n4 + 2] = f2tf(kv.z);
            sU[d * KSTR + n4 + 3] = f2tf(kv.w);
        }
        __syncthreads();
#pragma unroll
        for (int kk = 0; kk < 64; kk += 8) {
            unsigned af[4], bf[2];
            af[0] = sQ[(kk + tig) * QSTR + mloc];
            af[1] = sQ[(kk + tig) * QSTR + mloc + 8];
            af[2] = sQ[(kk + tig + 4) * QSTR + mloc];
            af[3] = sQ[(kk + tig + 4) * QSTR + mloc + 8];
            int n = wn * 8 + grp;
            bf[0] = sU[(kk + tig) * KSTR + n];
            bf[1] = sU[(kk + tig + 4) * KSTR + n];
            MMA_TF32(S[c], af, bf);
        }
    }

    // ---------------- mask + softmax stats ----------------
    const int nlat = nlp ? *nlp : 32;
    const int r0 = m0 + mloc;          // global rows r0, r0+8
    const bool lat0 = (r0 < nlat), lat1 = (r0 + 8 < nlat);
    const int mq0 = s_mods[r0], mq1 = s_mods[r0 + 8];

    float lmax[2] = {-3.0e38f, -3.0e38f};
#pragma unroll
    for (int c = 0; c < 8; c++) {
        int cb = c * 64 + wn * 8 + tig * 2;
        int k0m = s_mods[cb], k1m = s_mods[cb + 1];
        if (!(lat0 || mq0 == k0m)) S[c][0] = -3.0e38f;
        if (!(lat0 || mq0 == k1m)) S[c][1] = -3.0e38f;
        if (!(lat1 || mq1 == k0m)) S[c][2] = -3.0e38f;
        if (!(lat1 || mq1 == k1m)) S[c][3] = -3.0e38f;
        lmax[0] = fmaxf(lmax[0], fmaxf(S[c][0], S[c][1]));
        lmax[1] = fmaxf(lmax[1], fmaxf(S[c][2], S[c][3]));
    }
#pragma unroll
    for (int d = 1; d <= 2; d <<= 1) {
        lmax[0] = fmaxf(lmax[0], __shfl_xor_sync(0xffffffffu, lmax[0], d));
        lmax[1] = fmaxf(lmax[1], __shfl_xor_sync(0xffffffffu, lmax[1], d));
    }
    if (tig == 0) {
        s_red[w * 32 + mloc]     = lmax[0];
        s_red[w * 32 + mloc + 8] = lmax[1];
    }
    __syncthreads();
    if (tid < 32) {
        float m = -3.0e38f;
        int wb = tid >> 4;
#pragma unroll
        for (int k = 0; k < 8; k++) m = fmaxf(m, s_red[(k * 2 + wb) * 32 + tid]);
        s_rmax[tid] = m;
    }
    __syncthreads();

    const float rm0 = s_rmax[mloc], rm1 = s_rmax[mloc + 8];
    float lsum[2] = {0.0f, 0.0f};
#pragma unroll
    for (int c = 0; c < 8; c++) {
        S[c][0] = __expf(S[c][0] - rm0);
        S[c][1] = __expf(S[c][1] - rm0);
        S[c][2] = __expf(S[c][2] - rm1);
        S[c][3] = __expf(S[c][3] - rm1);
        lsum[0] += S[c][0] + S[c][1];
        lsum[1] += S[c][2] + S[c][3];
    }
#pragma unroll
    for (int d = 1; d <= 2; d <<= 1) {
        lsum[0] += __shfl_xor_sync(0xffffffffu, lsum[0], d);
        lsum[1] += __shfl_xor_sync(0xffffffffu, lsum[1], d);
    }
    if (tig == 0) {
        s_red[w * 32 + mloc]     = lsum[0];
        s_red[w * 32 + mloc + 8] = lsum[1];
    }
    __syncthreads();
    if (tid < 32) {
        float s = 0.0f;
        int wb = tid >> 4;
#pragma unroll
        for (int k = 0; k < 8; k++) s += s_red[(k * 2 + wb) * 32 + tid];
        s_rinv[tid] = 1.0f / s;
    }

    // ---------------- phase 2: O = P @ V ----------------
    unsigned* sP = sU;                  // [key][q] stride QSTR, 64 keys
    unsigned* sV = sU + 64 * QSTR;      // [key][d] stride KSTR

    float O[4] = {0.0f, 0.0f, 0.0f, 0.0f};
#pragma unroll
    for (int c = 0; c < 8; c++) {
        __syncthreads();
        {
            int cl = wn * 8 + tig * 2;
            sP[(cl + 0) * QSTR + mloc]     = f2tf(S[c][0]);
            sP[(cl + 1) * QSTR + mloc]     = f2tf(S[c][1]);
            sP[(cl + 0) * QSTR + mloc + 8] = f2tf(S[c][2]);
            sP[(cl + 1) * QSTR + mloc + 8] = f2tf(S[c][3]);
        }
#pragma unroll
        for (int rep = 0; rep < 2; rep++) {
            int t = rep * 512 + tid;
            int s = t >> 4, d4 = (t & 15) * 4;
            float4 v = *(const float4*)(Vp + (size_t)(c * 64 + s) * HDIM + d4);
            sV[s * KSTR + d4 + 0] = f2tf(v.x);
            sV[s * KSTR + d4 + 1] = f2tf(v.y);
            sV[s * KSTR + d4 + 2] = f2tf(v.z);
            sV[s * KSTR + d4 + 3] = f2tf(v.w);
        }
        __syncthreads();
#pragma unroll
        for (int kk = 0; kk < 64; kk += 8) {
            unsigned af[4], bf[2];
            af[0] = sP[(kk + tig) * QSTR + mloc];
            af[1] = sP[(kk + tig) * QSTR + mloc + 8];
            af[2] = sP[(kk + tig + 4) * QSTR + mloc];
            af[3] = sP[(kk + tig + 4) * QSTR + mloc + 8];
            int n = wn * 8 + grp;
            bf[0] = sV[(kk + tig) * KSTR + n];
            bf[1] = sV[(kk + tig + 4) * KSTR + n];
            MMA_TF32(O, af, bf);
        }
    }

    // epilogue: normalize rows and write ctx
    const float i0 = s_rinv[mloc], i1 = s_rinv[mloc + 8];
    const int d0 = wn * 8 + tig * 2;
    float* dst0 = g_CTX + (size_t)(bt * SEQ + m0 + mloc) * DMODEL + h * HDIM + d0;
    float* dst1 = g_CTX + (size_t)(bt * SEQ + m0 + mloc + 8) * DMODEL + h * HDIM + d0;
    dst0[0] = O[0] * i0;
    dst0[1] = O[1] * i0;
    dst1[0] = O[2] * i1;
    dst1[1] = O[3] * i1;
}

// =============================================================================
extern "C" void kernel_launch(void* const* d_in, const int* in_sizes, int n_in,
                              void* d_out, int out_size)
{
    const float* x  = (const float*)d_in[0];
    const float* Wq = (const float*)d_in[1];
    const float* bq = (const float*)d_in[2];
    const float* Wk = (const float*)d_in[3];
    const float* bk = (const float*)d_in[4];
    const float* Wv = (const float*)d_in[5];
    const float* bv = (const float*)d_in[6];
    const float* Wo = (const float*)d_in[7];
    const float* bo = (const float*)d_in[8];
    const int* mods = (const int*)d_in[9];
    const int* nlp  = (n_in > 10) ? (const int*)d_in[10] : nullptr;
    float* out = (float*)d_out;

    gemm768<<<dim3(6, 128), 256>>>(x, Wq, bq, nullptr, 0);
    gemm768<<<dim3(6, 128), 256>>>(x, Wk, bk, nullptr, 1);
    gemm768<<<dim3(6, 128), 256>>>(x, Wv, bv, nullptr, 2);
    attn_fused<<<dim3(SEQ / 32, NBATCH), 512>>>(mods, nlp);
    gemm768<<<dim3(6, 128), 256>>>(nullptr, Wo, bo, out, 3);
}

// round 6
// speedup vs baseline: 2.3162x; 1.0528x over previous
#include <cuda_runtime.h>
#include <math.h>

// Problem constants
#define MROWS  16384   // B*T*S = 32*512
#define DMODEL 768
#define SEQ    512
#define NHEAD  12
#define HDIM   64
#define NBATCH 384     // (B*T)*H = 32*12

// ---------------- scratch (static device memory; no allocation) --------------
__device__ float g_Q  [(size_t)NBATCH * SEQ * HDIM];   // [b*h][s][d]  (pre-scaled)
__device__ float g_Kt [(size_t)NBATCH * HDIM * SEQ];   // [b*h][d][s]  (transposed)
__device__ float g_V  [(size_t)NBATCH * SEQ * HDIM];   // [b*h][s][d]
__device__ float g_CTX[(size_t)MROWS * DMODEL];        // [row][h*64+d]

// ---------------- helpers ----------------
__device__ __forceinline__ unsigned f2tf(float f) {
    unsigned u;
    asm("cvt.rna.tf32.f32 %0, %1;" : "=r"(u) : "f"(f));
    return u;
}

__device__ __forceinline__ void cp16(unsigned dst, const void* src) {
    asm volatile("cp.async.ca.shared.global [%0], [%1], 16;" :: "r"(dst), "l"(src));
}

#define MMA_TF32(d, a, b)                                                          \
    asm volatile(                                                                  \
        "mma.sync.aligned.m16n8k8.row.col.f32.tf32.tf32.f32 "                      \
        "{%0,%1,%2,%3}, {%4,%5,%6,%7}, {%8,%9}, {%0,%1,%2,%3};"                    \
        : "+f"((d)[0]), "+f"((d)[1]), "+f"((d)[2]), "+f"((d)[3])                   \
        : "r"((a)[0]), "r"((a)[1]), "r"((a)[2]), "r"((a)[3]),                      \
          "r"((b)[0]), "r"((b)[1]))

// scatter for projection GEMM epilogues
__device__ __forceinline__ void scatter(int mode, int m, int n, float v,
                                        float* __restrict__ out) {
    int bt = m >> 9, s = m & 511;
    int h = n >> 6, d = n & 63;
    if (mode == 0) {
        g_Q[((size_t)(bt * NHEAD + h) * SEQ + s) * HDIM + d] = v * 0.125f;
    } else if (mode == 1) {
        g_Kt[((size_t)(bt * NHEAD + h) * HDIM + d) * SEQ + s] = v;
    } else if (mode == 2) {
        g_V[((size_t)(bt * NHEAD + h) * SEQ + s) * HDIM + d] = v;
    } else {
        out[(size_t)m * DMODEL + n] = v;
    }
}

// =============================================================================
// 128x128 tf32-MMA GEMM over K=768, cp.async double-buffered, 2 blocks/SM.
// =============================================================================
#define SA_STR 20
#define SB_STR 136
#define SA_SZ  (128 * SA_STR)
#define SB_SZ  (16 * SB_STR)

__global__ __launch_bounds__(256, 2) void gemm768(
    const float* __restrict__ A_in, const float* __restrict__ W,
    const float* __restrict__ bias, float* __restrict__ out, int mode)
{
    __shared__ float sA[2 * SA_SZ];
    __shared__ float sB[2 * SB_SZ];

    const float* __restrict__ A = (mode == 3) ? (const float*)g_CTX : A_in;

    const int tid  = threadIdx.x;
    const int lane = tid & 31, warp = tid >> 5;
    const int wm = warp & 1, wn = warp >> 1;
    const int grp = lane >> 2, tig = lane & 3;
    const int m0 = blockIdx.y * 128;
    const int n0 = blockIdx.x * 128;

    const unsigned sA_u32 = (unsigned)__cvta_generic_to_shared(sA);
    const unsigned sB_u32 = (unsigned)__cvta_generic_to_shared(sB);

    float acc[4][4][4];
#pragma unroll
    for (int i = 0; i < 4; i++)
#pragma unroll
        for (int j = 0; j < 4; j++)
#pragma unroll
            for (int e = 0; e < 4; e++) acc[i][j][e] = 0.0f;

#define G_LOAD_TILES(buf, k0)                                                     \
    {                                                                             \
        _Pragma("unroll")                                                         \
        for (int rep = 0; rep < 2; rep++) {                                       \
            int t = rep * 256 + tid;                                              \
            int r = t >> 2, c4 = (t & 3) * 4;                                     \
            cp16(sA_u32 + (unsigned)(((buf) * SA_SZ + r * SA_STR + c4) * 4),      \
                 A + (size_t)(m0 + r) * DMODEL + (k0) + c4);                      \
        }                                                                         \
        _Pragma("unroll")                                                         \
        for (int rep = 0; rep < 2; rep++) {                                       \
            int t = rep * 256 + tid;                                              \
            int r = t >> 5, c4 = (t & 31) * 4;                                    \
            cp16(sB_u32 + (unsigned)(((buf) * SB_SZ + r * SB_STR + c4) * 4),      \
                 W + (size_t)((k0) + r) * DMODEL + n0 + c4);                      \
        }                                                                         \
        asm volatile("cp.async.commit_group;" ::: "memory");                      \
    }

    G_LOAD_TILES(0, 0);

    int buf = 0;
    for (int k0 = 0; k0 < DMODEL; k0 += 16) {
        asm volatile("cp.async.wait_group 0;" ::: "memory");
        __syncthreads();
        if (k0 + 16 < DMODEL) G_LOAD_TILES(buf ^ 1, k0 + 16);

        const float* pA = sA + buf * SA_SZ;
        const float* pB = sB + buf * SB_SZ;
#pragma unroll
        for (int kk = 0; kk < 16; kk += 8) {
            unsigned af[4][4], bf[4][2];
#pragma unroll
            for (int mi = 0; mi < 4; mi++) {
                int m = wm * 64 + mi * 16 + grp;
                af[mi][0] = f2tf(pA[m * SA_STR + kk + tig]);
                af[mi][1] = f2tf(pA[(m + 8) * SA_STR + kk + tig]);
                af[mi][2] = f2tf(pA[m * SA_STR + kk + tig + 4]);
                af[mi][3] = f2tf(pA[(m + 8) * SA_STR + kk + tig + 4]);
            }
#pragma unroll
            for (int nj = 0; nj < 4; nj++) {
                int n = wn * 32 + nj * 8 + grp;
                bf[nj][0] = f2tf(pB[(kk + tig) * SB_STR + n]);
                bf[nj][1] = f2tf(pB[(kk + tig + 4) * SB_STR + n]);
            }
#pragma unroll
            for (int mi = 0; mi < 4; mi++)
#pragma unroll
                for (int nj = 0; nj < 4; nj++)
                    MMA_TF32(acc[mi][nj], af[mi], bf[nj]);
        }
        buf ^= 1;
    }

#pragma unroll
    for (int mi = 0; mi < 4; mi++) {
        int r0 = m0 + wm * 64 + mi * 16 + grp;
#pragma unroll
        for (int nj = 0; nj < 4; nj++) {
            int c0 = n0 + wn * 32 + nj * 8 + tig * 2;
            scatter(mode, r0,     c0,     acc[mi][nj][0] + bias[c0],     out);
            scatter(mode, r0,     c0 + 1, acc[mi][nj][1] + bias[c0 + 1], out);
            scatter(mode, r0 + 8, c0,     acc[mi][nj][2] + bias[c0],     out);
            scatter(mode, r0 + 8, c0 + 1, acc[mi][nj][3] + bias[c0 + 1], out);
        }
    }
#undef G_LOAD_TILES
}

// =============================================================================
// Fused attention v2: block = (head-batch, 64 q rows), 512 threads, 16 warps.
// Phase 1: S(64x512) = Q @ K^T in registers; K in 128-key cp.async chunks.
// Warp grid 2(m) x 8(n): warp tile m32 x n16 per chunk.
// Packed-pair smem layout for Q/P enables LDS.64 A-fragment loads.
// Phase 2: O(64x64) = P @ V; P round-trips smem; V via cp.async.
// Dynamic smem: 96768 bytes.
// =============================================================================
// word-offsets into dynamic smem
#define OFF_Q    0                    // [q][kpacked] stride 68, 64x68
#define OFF_K    4352                 // 2 bufs of [k][n] stride 136, 64x136 each
#define OFF_P    4352                 // phase2: [q][kpacked] stride 140, 64x140
#define OFF_V    13312                // [s][d] stride 72, 128x72
#define OFF_MODS 22528
#define OFF_RED  23040                // 16 x 64
#define OFF_RMAX 24064
#define OFF_RINV 24128
#define ATTN_SMEM_WORDS 24192
#define ATTN_SMEM_BYTES (ATTN_SMEM_WORDS * 4)

extern __shared__ unsigned dsm[];

__global__ __launch_bounds__(512, 1) void attn_fused(
    const int* __restrict__ mods, const int* __restrict__ nlp)
{
    unsigned* sQ     = dsm + OFF_Q;
    float*    sK     = (float*)(dsm + OFF_K);
    unsigned* sP     = dsm + OFF_P;
    float*    sV     = (float*)(dsm + OFF_V);
    int*      s_mods = (int*)(dsm + OFF_MODS);
    float*    s_red  = (float*)(dsm + OFF_RED);
    float*    s_rmax = (float*)(dsm + OFF_RMAX);
    float*    s_rinv = (float*)(dsm + OFF_RINV);

    const int tid  = threadIdx.x;
    const int lane = tid & 31, w = tid >> 5;
    const int grp  = lane >> 2, tig = lane & 3;
    const int wm = w & 1, wn = w >> 1;          // 2 x 8 warp grid
    const int batch = blockIdx.y;
    const int m0 = blockIdx.x * 64;
    const int bt = batch / NHEAD, h = batch % NHEAD;

    const float* __restrict__ Qp = g_Q  + (size_t)batch * SEQ * HDIM;
    const float* __restrict__ Kp = g_Kt + (size_t)batch * HDIM * SEQ;
    const float* __restrict__ Vp = g_V  + (size_t)batch * SEQ * HDIM;
    const unsigned smem_u32 = (unsigned)__cvta_generic_to_shared(dsm);

    s_mods[tid] = mods[tid];
    {   // Q tile, packed-pair layout: word q*68 + k8grp*8 + (k&3)*2 + ((k>>2)&1)
        int q = tid >> 3, j = tid & 7;
        const float* src = Qp + (size_t)(m0 + q) * HDIM + j * 8;
        float4 a = *(const float4*)src;
        float4 b = *(const float4*)(src + 4);
        unsigned* dst = sQ + q * 68 + j * 8;
        dst[0] = f2tf(a.x); dst[1] = f2tf(b.x);
        dst[2] = f2tf(a.y); dst[3] = f2tf(b.y);
        dst[4] = f2tf(a.z); dst[5] = f2tf(b.z);
        dst[6] = f2tf(a.w); dst[7] = f2tf(b.w);
    }

#define LOAD_K(buf, c)                                                            \
    {                                                                             \
        _Pragma("unroll")                                                         \
        for (int rep = 0; rep < 4; rep++) {                                       \
            int idx = rep * 512 + tid;                                            \
            int r = idx >> 5, c4 = (idx & 31) * 4;                                \
            cp16(smem_u32 + (unsigned)((OFF_K + (buf) * 8704 + r * 136 + c4) * 4),\
                 Kp + (size_t)r * SEQ + (c) * 128 + c4);                          \
        }                                                                         \
        asm volatile("cp.async.commit_group;" ::: "memory");                      \
    }

    LOAD_K(0, 0);

    float S[4][2][2][4];
#pragma unroll
    for (int c = 0; c < 4; c++)
#pragma unroll
        for (int i = 0; i < 2; i++)
#pragma unroll
            for (int j = 0; j < 2; j++)
#pragma unroll
                for (int e = 0; e < 4; e++) S[c][i][j][e] = 0.0f;

    const unsigned* qr0 = sQ + (wm * 32 + grp) * 68 + 2 * tig;
    const unsigned* qr1 = sQ + (wm * 32 + grp + 8) * 68 + 2 * tig;
    const unsigned* qr2 = sQ + (wm * 32 + grp + 16) * 68 + 2 * tig;
    const unsigned* qr3 = sQ + (wm * 32 + grp + 24) * 68 + 2 * tig;
    const int bn0 = wn * 16 + grp;

    // ---------------- phase 1 ----------------
#pragma unroll
    for (int c = 0; c < 4; c++) {
        asm volatile("cp.async.wait_group 0;" ::: "memory");
        __syncthreads();
        if (c < 3) LOAD_K((c + 1) & 1, c + 1);
        const float* pK = sK + (c & 1) * 8704;
#pragma unroll
        for (int kk = 0; kk < 64; kk += 8) {
            uint2 u00 = *(const uint2*)(qr0 + kk);
            uint2 u01 = *(const uint2*)(qr1 + kk);
            uint2 u10 = *(const uint2*)(qr2 + kk);
            uint2 u11 = *(const uint2*)(qr3 + kk);
            unsigned af0[4] = {u00.x, u01.x, u00.y, u01.y};
            unsigned af1[4] = {u10.x, u11.x, u10.y, u11.y};
            unsigned bf0[2] = { f2tf(pK[(kk + tig) * 136 + bn0]),
                                f2tf(pK[(kk + tig + 4) * 136 + bn0]) };
            unsigned bf1[2] = { f2tf(pK[(kk + tig) * 136 + bn0 + 8]),
                                f2tf(pK[(kk + tig + 4) * 136 + bn0 + 8]) };
            MMA_TF32(S[c][0][0], af0, bf0);
            MMA_TF32(S[c][0][1], af0, bf1);
            MMA_TF32(S[c][1][0], af1, bf0);
            MMA_TF32(S[c][1][1], af1, bf1);
        }
    }
#undef LOAD_K

    // ---------------- mask + softmax ----------------
    const int nlat = nlp ? *nlp : 32;
    int rloc[4]; int mq[4]; bool lat[4]; float lm[4];
#pragma unroll
    for (int rr = 0; rr < 4; rr++) {
        int mi = rr >> 1, hh = rr & 1;
        rloc[rr] = wm * 32 + mi * 16 + hh * 8 + grp;
        int rg = m0 + rloc[rr];
        lat[rr] = (rg < nlat);
        mq[rr] = s_mods[rg];
        lm[rr] = -3.0e38f;
    }
#pragma unroll
    for (int c = 0; c < 4; c++)
#pragma unroll
        for (int nj = 0; nj < 2; nj++) {
            int k0 = c * 128 + wn * 16 + nj * 8 + 2 * tig;
            int md0 = s_mods[k0], md1 = s_mods[k0 + 1];
#pragma unroll
            for (int rr = 0; rr < 4; rr++) {
                int mi = rr >> 1, hh = rr & 1;
                float& s0 = S[c][mi][nj][hh * 2 + 0];
                float& s1 = S[c][mi][nj][hh * 2 + 1];
                if (!(lat[rr] || mq[rr] == md0)) s0 = -3.0e38f;
                if (!(lat[rr] || mq[rr] == md1)) s1 = -3.0e38f;
                lm[rr] = fmaxf(lm[rr], fmaxf(s0, s1));
            }
        }
#pragma unroll
    for (int rr = 0; rr < 4; rr++) {
        lm[rr] = fmaxf(lm[rr], __shfl_xor_sync(0xffffffffu, lm[rr], 1));
        lm[rr] = fmaxf(lm[rr], __shfl_xor_sync(0xffffffffu, lm[rr], 2));
    }
    if (tig == 0) {
#pragma unroll
        for (int rr = 0; rr < 4; rr++) s_red[w * 64 + rloc[rr]] = lm[rr];
    }
    __syncthreads();
    if (tid < 64) {
        int wsel = tid >> 5;
        float m = -3.0e38f;
#pragma unroll
        for (int j = 0; j < 8; j++) m = fmaxf(m, s_red[(2 * j + wsel) * 64 + tid]);
        s_rmax[tid] = m;
    }
    __syncthreads();

    float rm[4], ls[4];
#pragma unroll
    for (int rr = 0; rr < 4; rr++) { rm[rr] = s_rmax[rloc[rr]]; ls[rr] = 0.0f; }
#pragma unroll
    for (int c = 0; c < 4; c++)
#pragma unroll
        for (int nj = 0; nj < 2; nj++)
#pragma unroll
            for (int rr = 0; rr < 4; rr++) {
                int mi = rr >> 1, hh = rr & 1;
                float& s0 = S[c][mi][nj][hh * 2 + 0];
                float& s1 = S[c][mi][nj][hh * 2 + 1];
                s0 = __expf(s0 - rm[rr]);
                s1 = __expf(s1 - rm[rr]);
                ls[rr] += s0 + s1;
            }
#pragma unroll
    for (int rr = 0; rr < 4; rr++) {
        ls[rr] += __shfl_xor_sync(0xffffffffu, ls[rr], 1);
        ls[rr] += __shfl_xor_sync(0xffffffffu, ls[rr], 2);
    }
    if (tig == 0) {
#pragma unroll
        for (int rr = 0; rr < 4; rr++) s_red[w * 64 + rloc[rr]] = ls[rr];
    }
    __syncthreads();
    if (tid < 64) {
        int wsel = tid >> 5;
        float s = 0.0f;
#pragma unroll
        for (int j = 0; j < 8; j++) s += s_red[(2 * j + wsel) * 64 + tid];
        s_rinv[tid] = 1.0f / s;
    }

    // ---------------- phase 2: O = P @ V ----------------
    float O0[4] = {0.0f, 0.0f, 0.0f, 0.0f};
    float O1[4] = {0.0f, 0.0f, 0.0f, 0.0f};
    const int vn = wn * 8 + grp;
    const unsigned* pr0 = sP + (wm * 32 + grp) * 140 + 2 * tig;
    const unsigned* pr1 = sP + (wm * 32 + grp + 8) * 140 + 2 * tig;
    const unsigned* pr2 = sP + (wm * 32 + grp + 16) * 140 + 2 * tig;
    const unsigned* pr3 = sP + (wm * 32 + grp + 24) * 140 + 2 * tig;

#pragma unroll
    for (int c = 0; c < 4; c++) {
        __syncthreads();
        // V chunk via cp.async (overlaps P stores)
#pragma unroll
        for (int rep = 0; rep < 4; rep++) {
            int idx = rep * 512 + tid;
            int r = idx >> 4, d4 = (idx & 15) * 4;
            cp16(smem_u32 + (unsigned)((OFF_V + r * 72 + d4) * 4),
                 Vp + (size_t)(c * 128 + r) * HDIM + d4);
        }
        asm volatile("cp.async.commit_group;" ::: "memory");
        // store P chunk (packed-pair layout)
#pragma unroll
        for (int nj = 0; nj < 2; nj++)
#pragma unroll
            for (int b = 0; b < 2; b++) {
                int kl = wn * 16 + nj * 8 + 2 * tig + b;
                int pos = (kl >> 3) * 8 + (kl & 3) * 2 + ((kl >> 2) & 1);
#pragma unroll
                for (int rr = 0; rr < 4; rr++) {
                    int mi = rr >> 1, hh = rr & 1;
                    sP[rloc[rr] * 140 + pos] = f2tf(S[c][mi][nj][hh * 2 + b]);
                }
            }
        asm volatile("cp.async.wait_group 0;" ::: "memory");
        __syncthreads();
#pragma unroll
        for (int kk = 0; kk < 128; kk += 8) {
            uint2 u00 = *(const uint2*)(pr0 + kk);
            uint2 u01 = *(const uint2*)(pr1 + kk);
            uint2 u10 = *(const uint2*)(pr2 + kk);
            uint2 u11 = *(const uint2*)(pr3 + kk);
            unsigned af0[4] = {u00.x, u01.x, u00.y, u01.y};
            unsigned af1[4] = {u10.x, u11.x, u10.y, u11.y};
            unsigned bf[2] = { f2tf(sV[(kk + tig) * 72 + vn]),
                               f2tf(sV[(kk + tig + 4) * 72 + vn]) };
            MMA_TF32(O0, af0, bf);
            MMA_TF32(O1, af1, bf);
        }
    }

    // epilogue: normalize and write ctx
#pragma unroll
    for (int rr = 0; rr < 4; rr++) {
        int mi = rr >> 1, hh = rr & 1;
        const float* Osel = mi ? O1 : O0;
        float inv = s_rinv[rloc[rr]];
        float2 val;
        val.x = Osel[hh * 2 + 0] * inv;
        val.y = Osel[hh * 2 + 1] * inv;
        int d0 = wn * 8 + 2 * tig;
        *(float2*)(g_CTX + (size_t)(bt * SEQ + m0 + rloc[rr]) * DMODEL
                   + h * HDIM + d0) = val;
    }
}

// =============================================================================
extern "C" void kernel_launch(void* const* d_in, const int* in_sizes, int n_in,
                              void* d_out, int out_size)
{
    const float* x  = (const float*)d_in[0];
    const float* Wq = (const float*)d_in[1];
    const float* bq = (const float*)d_in[2];
    const float* Wk = (const float*)d_in[3];
    const float* bk = (const float*)d_in[4];
    const float* Wv = (const float*)d_in[5];
    const float* bv = (const float*)d_in[6];
    const float* Wo = (const float*)d_in[7];
    const float* bo = (const float*)d_in[8];
    const int* mods = (const int*)d_in[9];
    const int* nlp  = (n_in > 10) ? (const int*)d_in[10] : nullptr;
    float* out = (float*)d_out;

    cudaFuncSetAttribute(attn_fused, cudaFuncAttributeMaxDynamicSharedMemorySize,
                         ATTN_SMEM_BYTES);

    gemm768<<<dim3(6, 128), 256>>>(x, Wq, bq, nullptr, 0);
    gemm768<<<dim3(6, 128), 256>>>(x, Wk, bk, nullptr, 1);
    gemm768<<<dim3(6, 128), 256>>>(x, Wv, bv, nullptr, 2);
    attn_fused<<<dim3(SEQ / 64, NBATCH), 512, ATTN_SMEM_BYTES>>>(mods, nlp);
    gemm768<<<dim3(6, 128), 256>>>(nullptr, Wo, bo, out, 3);
}